// round 6
// baseline (speedup 1.0000x reference)
#include <cuda_runtime.h>
#include <cuda_bf16.h>

#define NUM_SEG 32
#define C 256
#define C4 64   // float4 per row

// Scratch (allocation-free rule: __device__ globals).
// Invariant: g_sum and g_cnt are ZERO at entry to every kernel_launch.
// Zero-initialized at module load; se_mlp_kernel re-zeroes both after
// consuming them, so the invariant is restored by every launch
// (deterministic, no separate zero pass).
__device__ float  g_sum[NUM_SEG * C];
__device__ float  g_cnt[NUM_SEG];
__device__ float4 g_y4[NUM_SEG * C4];   // gates, float4-aligned

// ---------------------------------------------------------------------------
// Kernel 1: segment sum + segment counts, single-wave even partition at full
// occupancy. Grid = 152 SMs * 8 CTAs, __launch_bounds__(256, 8) => 64
// warps/SM, 32 regs/thread. Each block owns a contiguous equal slice of rows
// (no wave quantization, no tail). Walk in 128-row chunks: if
// idx[chunk_end-1] == cur (sorted => whole chunk one segment for this
// thread's rows) take the branch-free streaming path; else per-row fallback.
// Atomic flush only on segment change.
// Counts: the 4 threads with c4==0 (sub=0..3) each count the rows THEY
// process into THEIR cur segment -> exact even when per-thread cur diverges
// near boundaries. ~4 count atomics per chunk (noise).
// 256 threads = 64 float4 channel lanes x 4 subrows.
// ---------------------------------------------------------------------------
#define RED_BLOCKS (152 * 8)
#define CHUNK 128

__device__ __forceinline__ void flush_acc(int seg, int c4, float4 a0, float4 a1) {
    float* dst = &g_sum[seg * C + c4 * 4];
    atomicAdd(dst + 0, a0.x + a1.x);
    atomicAdd(dst + 1, a0.y + a1.y);
    atomicAdd(dst + 2, a0.z + a1.z);
    atomicAdd(dst + 3, a0.w + a1.w);
}

__global__ void __launch_bounds__(256, 8)
se_reduce_kernel(const float4* __restrict__ feats,
                 const int*    __restrict__ idx,
                 int N) {
    const int c4  = threadIdx.x & 63;   // channel float4 lane
    const int sub = threadIdx.x >> 6;   // 0..3

    // even contiguous partition of rows across blocks
    long r0 = (long)blockIdx.x * N / gridDim.x;
    long r1 = (long)(blockIdx.x + 1) * N / gridDim.x;
    if (r0 >= r1) return;

    float4 a0 = make_float4(0.f, 0.f, 0.f, 0.f);
    float4 a1 = make_float4(0.f, 0.f, 0.f, 0.f);
    int cur = __ldg(&idx[r0]);

    long cs = r0;
    while (cs < r1) {
        long ce = cs + CHUNK;
        if (ce > r1) ce = r1;
        int s_last = __ldg(&idx[ce - 1]);

        if (s_last == cur) {
            // fast path: this thread's rows in the chunk are all segment cur.
            if (c4 == 0) {
                // rows r in [cs+sub, ce) step 4
                float nrows = (float)((ce - (cs + sub) + 3) >> 2);
                atomicAdd(&g_cnt[cur], nrows);
            }
            const float4* p = feats + (cs + sub) * C4 + c4;
            long r = cs + sub;
            for (; r + 4 < ce; r += 8) {
                float4 v0 = __ldcs(p);
                float4 v1 = __ldcs(p + 4 * C4);
                a0.x += v0.x; a0.y += v0.y; a0.z += v0.z; a0.w += v0.w;
                a1.x += v1.x; a1.y += v1.y; a1.z += v1.z; a1.w += v1.w;
                p += 8 * C4;
            }
            for (; r < ce; r += 4) {
                float4 v = __ldcs(p);
                a0.x += v.x; a0.y += v.y; a0.z += v.z; a0.w += v.w;
                p += 4 * C4;
            }
        } else {
            // boundary chunk: per-row segment tracking (+ per-row counting
            // by the c4==0 threads)
            for (long r = cs + sub; r < ce; r += 4) {
                int s = __ldg(&idx[r]);
                float4 v = __ldcs(feats + r * C4 + c4);
                if (c4 == 0) atomicAdd(&g_cnt[s], 1.0f);
                if (s != cur) {
                    flush_acc(cur, c4, a0, a1);
                    a0 = v;
                    a1 = make_float4(0.f, 0.f, 0.f, 0.f);
                    cur = s;
                } else {
                    a0.x += v.x; a0.y += v.y; a0.z += v.z; a0.w += v.w;
                }
            }
        }
        cs = ce;
    }
    flush_acc(cur, c4, a0, a1);
}

// ---------------------------------------------------------------------------
// Kernel 2: one block per segment. Counts come from g_cnt (no binary search
// -> no serial DRAM pointer-chase). Mean, 256->16 GEMM (16-thread groups +
// shuffle reduce), ReLU, 16->256 GEMM, sigmoid. Re-zeroes its g_sum slice
// and g_cnt entry afterwards (restores launch invariant).
// ---------------------------------------------------------------------------
__global__ void se_mlp_kernel(const float* __restrict__ W1,
                              const float* __restrict__ b1,
                              const float* __restrict__ W2,
                              const float* __restrict__ b2) {
    const int s = blockIdx.x;
    const int t = threadIdx.x;
    __shared__ float sp[C];
    __shared__ float sh[16];
    __shared__ float s_inv;

    if (t == 0) {
        s_inv = 1.0f / fmaxf(g_cnt[s], 1.0f);
        g_cnt[s] = 0.0f;                 // consumer reset
    }
    __syncthreads();

    sp[t] = g_sum[s * C + t] * s_inv;
    g_sum[s * C + t] = 0.0f;             // consumer reset
    __syncthreads();

    // h[g] = relu(dot(sp, W1[:,g]) + b1[g]); 16 threads per output g
    {
        int g = t >> 4;       // output 0..15
        int l = t & 15;       // lane within group
        float acc = 0.0f;
        #pragma unroll
        for (int k = l; k < C; k += 16) acc += sp[k] * W1[k * 16 + g];
        #pragma unroll
        for (int off = 8; off; off >>= 1)
            acc += __shfl_down_sync(0xffffffffu, acc, off, 16);
        if (l == 0) sh[g] = fmaxf(acc + b1[g], 0.0f);
    }
    __syncthreads();

    // y[t] = sigmoid(dot(sh, W2[:,t]) + b2[t])
    float acc = b2[t];
    #pragma unroll
    for (int k = 0; k < 16; k++) acc += sh[k] * W2[k * C + t];
    ((float*)g_y4)[s * C + t] = 1.0f / (1.0f + __expf(-acc));
}

// ---------------------------------------------------------------------------
// Kernel 3: out = feats * y[batch_idx].  Flat float4 grid-stride, PLAIN
// loads/stores (cache-streaming hints measurably hurt this RMW stream).
// 298 us @ 84.9% DRAM — at the mixed-stream ceiling.
// ---------------------------------------------------------------------------
__global__ void se_scale_kernel(const float4* __restrict__ feats,
                                const int*    __restrict__ idx,
                                float4*       __restrict__ out,
                                long total4) {
    long stride = (long)gridDim.x * blockDim.x;
    for (long i = (long)blockIdx.x * blockDim.x + threadIdx.x;
         i < total4; i += stride) {
        int row = (int)(i >> 6);
        int c4  = (int)(i & 63);
        int s   = __ldg(&idx[row]);
        float4 v = feats[i];
        float4 g = g_y4[s * C4 + c4];
        float4 o;
        o.x = v.x * g.x; o.y = v.y * g.y; o.z = v.z * g.z; o.w = v.w * g.w;
        out[i] = o;
    }
}

// ---------------------------------------------------------------------------
extern "C" void kernel_launch(void* const* d_in, const int* in_sizes, int n_in,
                              void* d_out, int out_size) {
    const float* feats = (const float*)d_in[0];
    const int*   idx   = (const int*)  d_in[1];
    const float* W1    = (const float*)d_in[2];
    const float* b1    = (const float*)d_in[3];
    const float* W2    = (const float*)d_in[4];
    const float* b2    = (const float*)d_in[5];

    const int N = in_sizes[1];               // number of points
    const long total4 = (long)N * C4;

    se_reduce_kernel<<<RED_BLOCKS, 256>>>((const float4*)feats, idx, N);

    se_mlp_kernel<<<NUM_SEG, 256>>>(W1, b1, W2, b2);

    se_scale_kernel<<<2368, 256>>>((const float4*)feats, idx,
                                   (float4*)d_out, total4);
}